// round 12
// baseline (speedup 1.0000x reference)
#include <cuda_runtime.h>
#include <cuda_fp16.h>
#include <cstdint>

// Problem constants
#define BATCH 2
#define CHAN  128
#define NGRP  16
#define CPG   8
#define HH    64
#define WW    64
#define HW    (HH*WW)
#define NP    81
#define NDIL  4
#define NPHW  (NP*HW)

// Scratch cost volume, fp16 gin-PAIR packed: [zb(8)][gp(8)][d][h][w] __half2
__device__ __half2 g_cost2[(size_t)NDIL * BATCH * (NGRP / 2) * NPHW];
// nb repacked to fp16 gin pairs: [b(2)][gp(8)][c(8)][h][w] __half2  (2 MB)
__device__ __half2 g_nb2[(size_t)BATCH * 8 * CPG * HW];

// Conv slab: per d-slice [gp(8)][row(6)][col(72)] in __half2 words
//  GPW = 456 == 8 (mod 32): B-load banks = 8q + n, all distinct -> conflict-free
#define ROWW  72
#define GPW   456                  // 6*72=432 + 24 pad (half2 words)
#define SLABW (8 * GPW)            // 3648 half2 words per slice
#define NCHUNK 27                  // 27 taps (K=16 covers all gins per tap)
#define WF_BYTES (NCHUNK * 32 * 16)
#define SMEM_BYTES (2 * SLABW * 4 + WF_BYTES + 192)

// ---------------- helpers ----------------
__device__ __forceinline__ uint32_t smem_u32(const void* p) {
    uint32_t a;
    asm("{ .reg .u64 t; cvta.to.shared.u64 t, %1; cvt.u32.u64 %0, t; }"
        : "=r"(a) : "l"(p));
    return a;
}
__device__ __forceinline__ void cp_async16(uint32_t dst, const void* src) {
    asm volatile("cp.async.ca.shared.global [%0], [%1], 16;"
                 :: "r"(dst), "l"(src));
}
__device__ __forceinline__ uint32_t h2u(__half2 h) {
    return *reinterpret_cast<uint32_t*>(&h);
}
__device__ __forceinline__ void mma_f16(float c[4], uint4 a,
                                        uint32_t b0, uint32_t b1) {
    asm volatile(
        "mma.sync.aligned.m16n8k16.row.col.f32.f16.f16.f32 "
        "{%0,%1,%2,%3}, {%4,%5,%6,%7}, {%8,%9}, {%0,%1,%2,%3};"
        : "+f"(c[0]), "+f"(c[1]), "+f"(c[2]), "+f"(c[3])
        : "r"(a.x), "r"(a.y), "r"(a.z), "r"(a.w), "r"(b0), "r"(b1));
}

// ---------------------------------------------------------------------------
// Kernel 0: repack nb into fp16 gin-pair planes  [b][gp][c][h][w]
// ---------------------------------------------------------------------------
__global__ void repack_kernel(const float* __restrict__ nb) {
    const int m = blockIdx.x * 256 + threadIdx.x;   // 0 .. 2^19-1
    const int p  = m & (HW - 1);
    const int c  = (m >> 12) & 7;
    const int gp = (m >> 15) & 7;
    const int b  = m >> 18;
    const float* src = nb + ((size_t)b * CHAN + c * NGRP + 2 * gp) * HW + p;
    g_nb2[m] = __floats2half2_rn(src[0], src[HW]);
}

// ---------------------------------------------------------------------------
// Kernel 1: grouped windowed correlation + leaky ReLU(0.1)
// x1 fp32, x2 fp16 gin-pairs, fp32 accumulate, fp16-pair output
// ---------------------------------------------------------------------------
__global__ void corr_kernel(const float* __restrict__ x) {
    const int w  = threadIdx.x;
    const int h  = blockIdx.x * 4 + threadIdx.y;
    const int gp = blockIdx.y;               // 0..7
    const int zb = blockIdx.z;
    const int b  = zb & 1;
    const int dil = 1 << (zb >> 1);

    float a0[CPG], a1[CPG];
#pragma unroll
    for (int c = 0; c < CPG; c++) {
        a0[c] = x[(size_t)(b * CHAN + c * NGRP + 2 * gp) * HW + h * WW + w];
        a1[c] = x[(size_t)(b * CHAN + c * NGRP + 2 * gp + 1) * HW + h * WW + w];
    }

    const __half2* __restrict__ x2p =
        g_nb2 + ((size_t)b * 8 + gp) * CPG * HW;
    __half2* __restrict__ outp =
        g_cost2 + ((size_t)(zb * 8 + gp) * NP) * HW + h * WW + w;

#pragma unroll 1
    for (int di = 0; di < 9; di++) {
        const int y = h + (di - 4) * dil;
        const bool yok = ((unsigned)y < HH);
#pragma unroll 1
        for (int dj = 0; dj < 9; dj++) {
            const int xw = w + (dj - 4) * dil;
            float s0 = 0.f, s1 = 0.f;
            if (yok && (unsigned)xw < WW) {
                const int off = y * WW + xw;
#pragma unroll
                for (int c = 0; c < CPG; c++) {
                    float2 v = __half22float2(x2p[(size_t)c * HW + off]);
                    s0 += a0[c] * v.x;
                    s1 += a1[c] * v.y;
                }
            }
            s0 = (s0 > 0.f) ? s0 : 0.1f * s0;
            s1 = (s1 > 0.f) ? s1 : 0.1f * s1;
            outp[(size_t)(di * 9 + dj) * HW] =
                __float22half2_rn(make_float2(s0, s1));
        }
    }
}

// ---------------------------------------------------------------------------
// Kernel 2: 3x3x3 grouped conv via fp16 mma.sync m16n8k16, slice-streaming,
// 3 rotating fp32 accumulator sets, reg-lean inner loop for 4 CTAs/SM.
// grid = (16 strips, 8 zb, 4 d-segments) = 512 CTAs = one full wave @ 4/SM
// ---------------------------------------------------------------------------
__global__ void __launch_bounds__(128, 4)
conv_kernel(const float* __restrict__ conv_w,
            const float* __restrict__ conv_b,
            const float* __restrict__ bn_gamma,
            const float* __restrict__ bn_beta,
            const float* __restrict__ bn_mean,
            const float* __restrict__ bn_var,
            float* __restrict__ out) {
    extern __shared__ uint32_t sm[];
    uint32_t* s_slab = sm;                          // [2][SLABW] half2 words
    uint4*    s_wf   = (uint4*)(sm + 2 * SLABW);    // [27][32] A fragments
    float*    s_sc   = (float*)(s_wf + NCHUNK * 32);
    float*    s_sh   = s_sc + 16;

    const int tid  = threadIdx.x;
    const int lane = tid & 31;
    const int wid  = tid >> 5;               // output row in tile (0..3)
    const int zb   = blockIdx.y;
    const int dil_idx = zb >> 1;
    const int b    = zb & 1;
    const int h0   = blockIdx.x * 4;
    const int dseg = blockIdx.z;              // 0..3
    const int d0   = dseg ? (dseg * 20 + 1) : 0;   // 0,21,41,61
    const int dend = dseg * 20 + 21;               // 21,41,61,81

    const __half2* __restrict__ costz = g_cost2 + (size_t)zb * 8 * NPHW;

    // zero slab ring (halo/border stays zero forever)
    for (int i = tid; i < 2 * SLABW; i += 128) s_slab[i] = 0u;

    // pack fp16 A fragments: chunk t = kd*9+kh*3+kw; lane l: g0=l>>2, q=l&3
    {
        const float* __restrict__ wb = conv_w + (size_t)dil_idx * 16 * 16 * 27;
        for (int i = tid; i < NCHUNK * 32; i += 128) {
            int t = i >> 5, l = i & 31;
            int g0 = l >> 2, k0 = (l & 3) * 2;
            uint4 v;
            v.x = h2u(__float22half2_rn(make_float2(
                wb[((g0)     * 16 + k0)     * 27 + t],
                wb[((g0)     * 16 + k0 + 1) * 27 + t])));
            v.y = h2u(__float22half2_rn(make_float2(
                wb[((g0 + 8) * 16 + k0)     * 27 + t],
                wb[((g0 + 8) * 16 + k0 + 1) * 27 + t])));
            v.z = h2u(__float22half2_rn(make_float2(
                wb[((g0)     * 16 + k0 + 8) * 27 + t],
                wb[((g0)     * 16 + k0 + 9) * 27 + t])));
            v.w = h2u(__float22half2_rn(make_float2(
                wb[((g0 + 8) * 16 + k0 + 8) * 27 + t],
                wb[((g0 + 8) * 16 + k0 + 9) * 27 + t])));
            s_wf[i] = v;
        }
    }
    if (tid < NGRP) {
        int gi = dil_idx * NGRP + tid;
        float inv = bn_gamma[gi] * rsqrtf(bn_var[gi] + 1e-5f);
        s_sc[tid] = inv;
        s_sh[tid] = (conv_b[gi] - bn_mean[gi]) * inv + bn_beta[gi];
    }
    __syncthreads();

    const uint32_t slab_base = smem_u32(s_slab);
    // stage one d-slice: 8 gp x 6 rows x 16 segs x 16B = 768 cp.async
    auto stage = [&](int s) {
        uint32_t dslot = slab_base + (uint32_t)((s & 1) * SLABW) * 4;
        const __half2* __restrict__ src0 = costz + (size_t)s * HW;
#pragma unroll
        for (int k = 0; k < 6; k++) {
            int o = tid + k * 128;            // 768 ops
            int gp = o / 96;
            int rem = o - gp * 96;
            int r = rem >> 4, seg = rem & 15;
            int hg = h0 - 1 + r;
            if ((unsigned)hg < HH)
                cp_async16(dslot + (uint32_t)(gp * GPW + r * ROWW + 4 +
                                              seg * 4) * 4,
                           src0 + (size_t)gp * NPHW + hg * WW + seg * 4);
        }
        asm volatile("cp.async.commit_group;");
    };

    // B-load lane base: gp row = q = lane&3, px-in-chunk = n = lane>>2
    const int bq = (lane & 3) * GPW + (lane >> 2);
    const int g0 = lane >> 2;
    const float sc0 = s_sc[g0], sh0 = s_sh[g0];
    const float sc8 = s_sc[g0 + 8], sh8 = s_sh[g0 + 8];

    // three rotating accumulator sets (d = s+1 / s / s-1), 8 n-chunks each
    float accA[8][4], accB[8][4], accC[8][4];
#pragma unroll
    for (int nc = 0; nc < 8; nc++)
#pragma unroll
        for (int j = 0; j < 4; j++) {
            accA[nc][j] = 0.f; accB[nc][j] = 0.f; accC[nc][j] = 0.f;
        }

    // reg-lean compute: A frags per tap (12 regs), b0/b1 per nc (2 regs)
    auto compute = [&](const uint32_t* slot, bool do0, bool do1, bool do2) {
#pragma unroll
        for (int kh = 0; kh < 3; kh++) {
#pragma unroll
            for (int kw = 0; kw < 3; kw++) {
                const uint32_t* baddr =
                    slot + (wid + kh) * ROWW + (3 + kw) + bq;
                const int t = kh * 3 + kw;
                uint4 a0, a1, a2;
                if (do0) a0 = s_wf[t * 32 + lane];
                if (do1) a1 = s_wf[(9 + t) * 32 + lane];
                if (do2) a2 = s_wf[(18 + t) * 32 + lane];
#pragma unroll
                for (int nc = 0; nc < 8; nc++) {
                    const uint32_t b0 = baddr[nc * 8];
                    const uint32_t b1 = baddr[nc * 8 + 4 * GPW];
                    if (do0) mma_f16(accA[nc], a0, b0, b1);
                    if (do1) mma_f16(accB[nc], a1, b0, b1);
                    if (do2) mma_f16(accC[nc], a2, b0, b1);
                }
            }
        }
    };

    const size_t obase =
        ((size_t)(b * (NDIL * NGRP) + dil_idx * NGRP) * NP) * HW +
        (size_t)(h0 + wid) * WW;
    auto writeout = [&](int d, float a[8][4]) {
        const size_t ob = obase + (size_t)d * HW;
#pragma unroll
        for (int nc = 0; nc < 8; nc++) {
            const int px = nc * 8 + (lane & 3) * 2;
            float2 v0, v1;
            v0.x = fmaxf(a[nc][0] * sc0 + sh0, 0.f);
            v0.y = fmaxf(a[nc][1] * sc0 + sh0, 0.f);
            v1.x = fmaxf(a[nc][2] * sc8 + sh8, 0.f);
            v1.y = fmaxf(a[nc][3] * sc8 + sh8, 0.f);
            *(float2*)&out[ob + (size_t)g0 * NPHW + px] = v0;
            *(float2*)&out[ob + (size_t)(g0 + 8) * NPHW + px] = v1;
        }
    };

    const int s_lo = (d0 > 0) ? d0 - 1 : 0;
    const int s_hi = (dend < NP) ? dend : NP - 1;   // inclusive

    stage(s_lo);
    stage(s_lo + 1);

#pragma unroll 1
    for (int s = s_lo; s <= s_hi; s++) {
        if (s < s_hi) asm volatile("cp.async.wait_group 1;");
        else          asm volatile("cp.async.wait_group 0;");
        __syncthreads();

        const uint32_t* slot = s_slab + (s & 1) * SLABW;
        const bool do0 = (s + 1 >= d0) && (s + 1 < dend);
        const bool do1 = (s >= d0) && (s < dend);
        const bool do2 = (s - 1 >= d0);
        if (do0 && do1 && do2)
            compute(slot, true, true, true);          // branch-free hot path
        else
            compute(slot, do0, do1, do2);

        __syncthreads();          // slot (s) reads done before staging s+2
        if (s + 2 <= s_hi) stage(s + 2);

        if (s > d0) writeout(s - 1, accC);
        // rotate: C <- B, B <- A, A <- 0
#pragma unroll
        for (int nc = 0; nc < 8; nc++)
#pragma unroll
            for (int j = 0; j < 4; j++) {
                accC[nc][j] = accB[nc][j];
                accB[nc][j] = accA[nc][j];
                accA[nc][j] = 0.f;
            }
    }
    if (s_hi < dend) writeout(s_hi, accC);   // last seg: d = NP-1
}

// ---------------------------------------------------------------------------
extern "C" void kernel_launch(void* const* d_in, const int* in_sizes, int n_in,
                              void* d_out, int out_size) {
    const float* x  = (const float*)d_in[0];
    const float* nb = (const float*)d_in[1];
    const float* cw = (const float*)d_in[2];
    const float* cb = (const float*)d_in[3];
    const float* gm = (const float*)d_in[4];
    const float* bt = (const float*)d_in[5];
    const float* mn = (const float*)d_in[6];
    const float* vr = (const float*)d_in[7];
    float* out = (float*)d_out;

    // repack nb -> fp16 gin pairs
    repack_kernel<<<2048, 256>>>(nb);

    // correlation + leaky relu -> g_cost2 (fp16 pairs)
    dim3 cb1(64, 4);
    dim3 cg1(HH / 4, NGRP / 2, NDIL * BATCH);
    corr_kernel<<<cg1, cb1>>>(x);

    cudaFuncSetAttribute(conv_kernel,
                         cudaFuncAttributeMaxDynamicSharedMemorySize,
                         SMEM_BYTES);
    dim3 cg2(HH / 4, NDIL * BATCH, 4);     // 16 strips x 8 x 4 d-segments
    conv_kernel<<<cg2, 128, SMEM_BYTES>>>(cw, cb, gm, bt, mn, vr, out);
}

// round 13
// speedup vs baseline: 1.1956x; 1.1956x over previous
#include <cuda_runtime.h>
#include <cuda_fp16.h>
#include <cstdint>

// Problem constants
#define BATCH 2
#define CHAN  128
#define NGRP  16
#define CPG   8
#define HH    64
#define WW    64
#define HW    (HH*WW)
#define NP    81
#define NDIL  4
#define NPHW  (NP*HW)

// Scratch cost volume, fp16 gin-PAIR packed: [zb(8)][gp(8)][d][h][w] __half2
__device__ __half2 g_cost2[(size_t)NDIL * BATCH * (NGRP / 2) * NPHW];
// nb repacked, channel-interleaved: [b(2)][gp(8)][p(HW)][c(8)] __half2 (2 MB)
// -> all 8 channels of one (gp,pixel) are 32B contiguous: 2 LDG.128 per disp
__device__ __half2 g_nb2[(size_t)BATCH * 8 * HW * CPG];

// Conv slab: per d-slice [gp(8)][row(6)][col(72)] in __half2 words
//  GPW = 456 == 8 (mod 32): B-load banks = 8q + n, all distinct -> conflict-free
#define ROWW  72
#define GPW   456                  // 6*72=432 + 24 pad (half2 words)
#define SLABW (8 * GPW)            // 3648 half2 words per slice
#define NCHUNK 27                  // 27 taps (K=16 covers all gins per tap)
#define WF_BYTES (NCHUNK * 32 * 16)
#define SMEM_BYTES (2 * SLABW * 4 + WF_BYTES + 192)

// ---------------- helpers ----------------
__device__ __forceinline__ uint32_t smem_u32(const void* p) {
    uint32_t a;
    asm("{ .reg .u64 t; cvta.to.shared.u64 t, %1; cvt.u32.u64 %0, t; }"
        : "=r"(a) : "l"(p));
    return a;
}
__device__ __forceinline__ void cp_async16(uint32_t dst, const void* src) {
    asm volatile("cp.async.ca.shared.global [%0], [%1], 16;"
                 :: "r"(dst), "l"(src));
}
__device__ __forceinline__ uint32_t h2u(__half2 h) {
    return *reinterpret_cast<uint32_t*>(&h);
}
__device__ __forceinline__ void mma_f16(float c[4], const uint32_t a[4],
                                        uint32_t b0, uint32_t b1) {
    asm volatile(
        "mma.sync.aligned.m16n8k16.row.col.f32.f16.f16.f32 "
        "{%0,%1,%2,%3}, {%4,%5,%6,%7}, {%8,%9}, {%0,%1,%2,%3};"
        : "+f"(c[0]), "+f"(c[1]), "+f"(c[2]), "+f"(c[3])
        : "r"(a[0]), "r"(a[1]), "r"(a[2]), "r"(a[3]), "r"(b0), "r"(b1));
}

// ---------------------------------------------------------------------------
// Kernel 0: repack nb -> [b][gp][p][c] fp16 gin-pairs (writes coalesced)
// ---------------------------------------------------------------------------
__global__ void repack_kernel(const float* __restrict__ nb) {
    const int m = blockIdx.x * 256 + threadIdx.x;   // 0 .. 2^19-1
    const int c  = m & 7;
    const int p  = (m >> 3) & (HW - 1);
    const int gp = (m >> 15) & 7;
    const int b  = m >> 18;
    const float* src = nb + ((size_t)b * CHAN + c * NGRP + 2 * gp) * HW + p;
    g_nb2[m] = __floats2half2_rn(src[0], src[HW]);
}

// ---------------------------------------------------------------------------
// Kernel 1: grouped windowed correlation + leaky ReLU(0.1)
// x1 fp32, x2 fp16 channel-interleaved (2 LDG.128 per disp), fp32 accumulate
// ---------------------------------------------------------------------------
__global__ void corr_kernel(const float* __restrict__ x) {
    const int w  = threadIdx.x;
    const int h  = blockIdx.x * 4 + threadIdx.y;
    const int gp = blockIdx.y;               // 0..7
    const int zb = blockIdx.z;
    const int b  = zb & 1;
    const int dil = 1 << (zb >> 1);

    float a0[CPG], a1[CPG];
#pragma unroll
    for (int c = 0; c < CPG; c++) {
        a0[c] = x[(size_t)(b * CHAN + c * NGRP + 2 * gp) * HW + h * WW + w];
        a1[c] = x[(size_t)(b * CHAN + c * NGRP + 2 * gp + 1) * HW + h * WW + w];
    }

    const __half2* __restrict__ x2p =
        g_nb2 + ((size_t)(b * 8 + gp) * HW) * CPG;
    __half2* __restrict__ outp =
        g_cost2 + ((size_t)(zb * 8 + gp) * NP) * HW + h * WW + w;

#pragma unroll 1
    for (int di = 0; di < 9; di++) {
        const int y = h + (di - 4) * dil;
        const bool yok = ((unsigned)y < HH);
#pragma unroll 1
        for (int dj = 0; dj < 9; dj++) {
            const int xw = w + (dj - 4) * dil;
            float s0 = 0.f, s1 = 0.f;
            if (yok && (unsigned)xw < WW) {
                const int off = y * WW + xw;
                const uint4* q = (const uint4*)(x2p + (size_t)off * CPG);
                uint4 u0 = q[0], u1 = q[1];
                __half2 hv[8];
                *(uint4*)&hv[0] = u0;
                *(uint4*)&hv[4] = u1;
#pragma unroll
                for (int c = 0; c < CPG; c++) {
                    float2 v = __half22float2(hv[c]);
                    s0 += a0[c] * v.x;
                    s1 += a1[c] * v.y;
                }
            }
            s0 = (s0 > 0.f) ? s0 : 0.1f * s0;
            s1 = (s1 > 0.f) ? s1 : 0.1f * s1;
            outp[(size_t)(di * 9 + dj) * HW] =
                __float22half2_rn(make_float2(s0, s1));
        }
    }
}

// ---------------------------------------------------------------------------
// Kernel 2: 3x3x3 grouped conv via fp16 mma.sync m16n8k16, slice-streaming
// with 3 rotating fp32 accumulator sets. Warp = 1 row x 64 px. (R11 config)
// grid = (16 strips, 8 zb, 3 d-segments) = 384 CTAs
// ---------------------------------------------------------------------------
__global__ void __launch_bounds__(128, 3)
conv_kernel(const float* __restrict__ conv_w,
            const float* __restrict__ conv_b,
            const float* __restrict__ bn_gamma,
            const float* __restrict__ bn_beta,
            const float* __restrict__ bn_mean,
            const float* __restrict__ bn_var,
            float* __restrict__ out) {
    extern __shared__ uint32_t sm[];
    uint32_t* s_slab = sm;                          // [2][SLABW] half2 words
    uint4*    s_wf   = (uint4*)(sm + 2 * SLABW);    // [27][32] A fragments
    float*    s_sc   = (float*)(s_wf + NCHUNK * 32);
    float*    s_sh   = s_sc + 16;

    const int tid  = threadIdx.x;
    const int lane = tid & 31;
    const int wid  = tid >> 5;               // output row in tile (0..3)
    const int zb   = blockIdx.y;
    const int dil_idx = zb >> 1;
    const int b    = zb & 1;
    const int h0   = blockIdx.x * 4;
    const int dseg = blockIdx.z;
    const int d0   = dseg * 27;
    const int dend = d0 + 27;                // [d0, dend)

    const __half2* __restrict__ costz = g_cost2 + (size_t)zb * 8 * NPHW;

    // zero slab ring (halo/border stays zero forever)
    for (int i = tid; i < 2 * SLABW; i += 128) s_slab[i] = 0u;

    // pack fp16 A fragments: chunk t = kd*9+kh*3+kw; lane l: g0=l>>2, q=l&3
    {
        const float* __restrict__ wb = conv_w + (size_t)dil_idx * 16 * 16 * 27;
        for (int i = tid; i < NCHUNK * 32; i += 128) {
            int t = i >> 5, l = i & 31;
            int g0 = l >> 2, k0 = (l & 3) * 2;
            uint4 v;
            v.x = h2u(__float22half2_rn(make_float2(
                wb[((g0)     * 16 + k0)     * 27 + t],
                wb[((g0)     * 16 + k0 + 1) * 27 + t])));
            v.y = h2u(__float22half2_rn(make_float2(
                wb[((g0 + 8) * 16 + k0)     * 27 + t],
                wb[((g0 + 8) * 16 + k0 + 1) * 27 + t])));
            v.z = h2u(__float22half2_rn(make_float2(
                wb[((g0)     * 16 + k0 + 8) * 27 + t],
                wb[((g0)     * 16 + k0 + 9) * 27 + t])));
            v.w = h2u(__float22half2_rn(make_float2(
                wb[((g0 + 8) * 16 + k0 + 8) * 27 + t],
                wb[((g0 + 8) * 16 + k0 + 9) * 27 + t])));
            s_wf[i] = v;
        }
    }
    if (tid < NGRP) {
        int gi = dil_idx * NGRP + tid;
        float inv = bn_gamma[gi] * rsqrtf(bn_var[gi] + 1e-5f);
        s_sc[tid] = inv;
        s_sh[tid] = (conv_b[gi] - bn_mean[gi]) * inv + bn_beta[gi];
    }
    __syncthreads();

    const uint32_t slab_base = smem_u32(s_slab);
    // stage one d-slice: 8 gp x 6 rows x 16 segs x 16B = 768 cp.async
    auto stage = [&](int s) {
        uint32_t dslot = slab_base + (uint32_t)((s & 1) * SLABW) * 4;
        const __half2* __restrict__ src0 = costz + (size_t)s * HW;
#pragma unroll
        for (int k = 0; k < 6; k++) {
            int o = tid + k * 128;            // 768 ops
            int gp = o / 96;
            int rem = o - gp * 96;
            int r = rem >> 4, seg = rem & 15;
            int hg = h0 - 1 + r;
            if ((unsigned)hg < HH)
                cp_async16(dslot + (uint32_t)(gp * GPW + r * ROWW + 4 +
                                              seg * 4) * 4,
                           src0 + (size_t)gp * NPHW + hg * WW + seg * 4);
        }
        asm volatile("cp.async.commit_group;");
    };

    // B-load lane base: gp row = q = lane&3, px-in-chunk = n = lane>>2
    const int bq = (lane & 3) * GPW + (lane >> 2);
    const int g0 = lane >> 2;
    const float sc0 = s_sc[g0], sh0 = s_sh[g0];
    const float sc8 = s_sc[g0 + 8], sh8 = s_sh[g0 + 8];

    // three rotating accumulator sets (d = s+1 / s / s-1), 8 n-chunks each
    float accA[8][4], accB[8][4], accC[8][4];
#pragma unroll
    for (int nc = 0; nc < 8; nc++)
#pragma unroll
        for (int j = 0; j < 4; j++) {
            accA[nc][j] = 0.f; accB[nc][j] = 0.f; accC[nc][j] = 0.f;
        }

    auto compute = [&](const uint32_t* slot, bool do0, bool do1, bool do2) {
#pragma unroll
        for (int kh = 0; kh < 3; kh++) {
#pragma unroll
            for (int kw = 0; kw < 3; kw++) {
                const uint32_t* baddr =
                    slot + (wid + kh) * ROWW + (3 + kw) + bq;
                uint32_t B0[8], B1[8];
#pragma unroll
                for (int nc = 0; nc < 8; nc++) {
                    B0[nc] = baddr[nc * 8];
                    B1[nc] = baddr[nc * 8 + 4 * GPW];
                }
                const int t = kh * 3 + kw;
                if (do0) {
                    uint4 av = s_wf[t * 32 + lane];            // kd = 0
                    uint32_t A[4] = {av.x, av.y, av.z, av.w};
#pragma unroll
                    for (int nc = 0; nc < 8; nc++)
                        mma_f16(accA[nc], A, B0[nc], B1[nc]);
                }
                if (do1) {
                    uint4 av = s_wf[(9 + t) * 32 + lane];      // kd = 1
                    uint32_t A[4] = {av.x, av.y, av.z, av.w};
#pragma unroll
                    for (int nc = 0; nc < 8; nc++)
                        mma_f16(accB[nc], A, B0[nc], B1[nc]);
                }
                if (do2) {
                    uint4 av = s_wf[(18 + t) * 32 + lane];     // kd = 2
                    uint32_t A[4] = {av.x, av.y, av.z, av.w};
#pragma unroll
                    for (int nc = 0; nc < 8; nc++)
                        mma_f16(accC[nc], A, B0[nc], B1[nc]);
                }
            }
        }
    };

    const size_t obase =
        ((size_t)(b * (NDIL * NGRP) + dil_idx * NGRP) * NP) * HW +
        (size_t)(h0 + wid) * WW;
    auto writeout = [&](int d, float a[8][4]) {
        const size_t ob = obase + (size_t)d * HW;
#pragma unroll
        for (int nc = 0; nc < 8; nc++) {
            const int px = nc * 8 + (lane & 3) * 2;
            float2 v0, v1;
            v0.x = fmaxf(a[nc][0] * sc0 + sh0, 0.f);
            v0.y = fmaxf(a[nc][1] * sc0 + sh0, 0.f);
            v1.x = fmaxf(a[nc][2] * sc8 + sh8, 0.f);
            v1.y = fmaxf(a[nc][3] * sc8 + sh8, 0.f);
            *(float2*)&out[ob + (size_t)g0 * NPHW + px] = v0;
            *(float2*)&out[ob + (size_t)(g0 + 8) * NPHW + px] = v1;
        }
    };

    const int s_lo = (d0 > 0) ? d0 - 1 : 0;
    const int s_hi = (dend < NP) ? dend : NP - 1;   // inclusive

    stage(s_lo);
    stage(s_lo + 1);

#pragma unroll 1
    for (int s = s_lo; s <= s_hi; s++) {
        if (s < s_hi) asm volatile("cp.async.wait_group 1;");
        else          asm volatile("cp.async.wait_group 0;");
        __syncthreads();

        const uint32_t* slot = s_slab + (s & 1) * SLABW;
        const bool do0 = (s + 1 >= d0) && (s + 1 < dend);
        const bool do1 = (s >= d0) && (s < dend);
        const bool do2 = (s - 1 >= d0);
        if (do0 && do1 && do2)
            compute(slot, true, true, true);          // branch-free hot path
        else
            compute(slot, do0, do1, do2);

        __syncthreads();          // slot (s) reads done before staging s+2
        if (s + 2 <= s_hi) stage(s + 2);

        if (s > d0) writeout(s - 1, accC);
        // rotate: C <- B, B <- A, A <- 0
#pragma unroll
        for (int nc = 0; nc < 8; nc++)
#pragma unroll
            for (int j = 0; j < 4; j++) {
                accC[nc][j] = accB[nc][j];
                accB[nc][j] = accA[nc][j];
                accA[nc][j] = 0.f;
            }
    }
    if (s_hi < dend) writeout(s_hi, accC);   // last CTA of the seg: d = NP-1
}

// ---------------------------------------------------------------------------
extern "C" void kernel_launch(void* const* d_in, const int* in_sizes, int n_in,
                              void* d_out, int out_size) {
    const float* x  = (const float*)d_in[0];
    const float* nb = (const float*)d_in[1];
    const float* cw = (const float*)d_in[2];
    const float* cb = (const float*)d_in[3];
    const float* gm = (const float*)d_in[4];
    const float* bt = (const float*)d_in[5];
    const float* mn = (const float*)d_in[6];
    const float* vr = (const float*)d_in[7];
    float* out = (float*)d_out;

    // repack nb -> fp16 gin pairs, channel-interleaved
    repack_kernel<<<2048, 256>>>(nb);

    // correlation + leaky relu -> g_cost2 (fp16 pairs)
    dim3 cb1(64, 4);
    dim3 cg1(HH / 4, NGRP / 2, NDIL * BATCH);
    corr_kernel<<<cg1, cb1>>>(x);

    cudaFuncSetAttribute(conv_kernel,
                         cudaFuncAttributeMaxDynamicSharedMemorySize,
                         SMEM_BYTES);
    dim3 cg2(HH / 4, NDIL * BATCH, 3);     // 16 strips x 8 x 3 d-segments
    conv_kernel<<<cg2, 128, SMEM_BYTES>>>(cw, cb, gm, bt, mn, vr, out);
}